// round 15
// baseline (speedup 1.0000x reference)
#include <cuda_runtime.h>
#include <cuda_fp16.h>
#include <cstdint>

// ConvEmbedding: out[n,i] = normalize_row( sum_k w[i,k]*x[n,i+k] + b[i] )
// C = X(16384x2048) @ W_band(512x2048)^T, fp16 inputs, fp32 accumulation.
// R15: R14 + prep with MLP=8 (32 floats/thread, 8 front-batched LDG.128).

#define N_ROWS 16384
#define D_DIM  2048
#define E_DIM  512
#define K_DIM  1537

#define BM 128
#define BN 128
#define BK 64
#define PITCH 72                 // fp16 elems per smem row (144 B)
#define NITER 26                 // 1664 / 64, uniform for every E tile
#define THREADS 256
#define STAGES 3

#define TILE_SMEM (BM * PITCH * 2)           // 18432 B per tile
#define STAGE_SMEM (2 * TILE_SMEM)           // A, B = 36864 B
#define SMEM_BYTES (STAGES * STAGE_SMEM)     // 110592 B

#define CONV_BLOCKS 4096                     // N_ROWS*D_DIM/(256*32)

// ---------------- scratch (device globals) ----------------------------------
__device__ __half g_Xh[(size_t)N_ROWS * D_DIM];
__device__ __half g_Wh[(size_t)E_DIM * D_DIM];

// ---------------- kernel 1: fused prep (convert X + build banded W) ----------
// X-convert: 32 fp32 per thread as four independent 32B streams (MLP=8).
__global__ __launch_bounds__(256)
void prep_kernel(const float* __restrict__ x, const float* __restrict__ w) {
    const int blk = blockIdx.x;
    if (blk < CONV_BLOCKS) {
        const size_t base = ((size_t)blk * 256 + threadIdx.x) * 8;
        const size_t quarter = (size_t)CONV_BLOCKS * 256 * 8;   // stream stride
        float4 L[8];
        #pragma unroll
        for (int s = 0; s < 4; s++) {
            L[s * 2 + 0] = *reinterpret_cast<const float4*>(x + s * quarter + base);
            L[s * 2 + 1] = *reinterpret_cast<const float4*>(x + s * quarter + base + 4);
        }
        #pragma unroll
        for (int s = 0; s < 4; s++) {
            __half2 h[4];
            h[0] = __float22half2_rn(make_float2(L[s*2].x,   L[s*2].y));
            h[1] = __float22half2_rn(make_float2(L[s*2].z,   L[s*2].w));
            h[2] = __float22half2_rn(make_float2(L[s*2+1].x, L[s*2+1].y));
            h[3] = __float22half2_rn(make_float2(L[s*2+1].z, L[s*2+1].w));
            *reinterpret_cast<uint4*>(&g_Xh[s * quarter + base]) = *reinterpret_cast<uint4*>(h);
        }
    } else {
        const int i = blk - CONV_BLOCKS;   // 0..511
        const float* wrow = w + (size_t)i * K_DIM;
        for (int c = threadIdx.x; c < D_DIM; c += 256) {
            const int k = c - i;
            const float val = (k >= 0 && k < K_DIM) ? wrow[k] : 0.0f;
            g_Wh[(size_t)i * D_DIM + c] = __float2half_rn(val);
        }
    }
}

// ---------------- mma helpers ------------------------------------------------
__device__ __forceinline__ void ldm_x4(uint32_t* r, uint32_t saddr) {
    asm volatile("ldmatrix.sync.aligned.m8n8.x4.shared.b16 {%0,%1,%2,%3}, [%4];"
                 : "=r"(r[0]), "=r"(r[1]), "=r"(r[2]), "=r"(r[3]) : "r"(saddr));
}
__device__ __forceinline__ void mma_f16(float* d, const uint32_t* a, const uint32_t* b) {
    asm volatile(
        "mma.sync.aligned.m16n8k16.row.col.f32.f16.f16.f32 "
        "{%0,%1,%2,%3}, {%4,%5,%6,%7}, {%8,%9}, {%0,%1,%2,%3};"
        : "+f"(d[0]), "+f"(d[1]), "+f"(d[2]), "+f"(d[3])
        : "r"(a[0]), "r"(a[1]), "r"(a[2]), "r"(a[3]), "r"(b[0]), "r"(b[1]));
}
__device__ __forceinline__ void cp_async16(uint32_t saddr, const void* gaddr) {
    asm volatile("cp.async.cg.shared.global [%0], [%1], 16;" :: "r"(saddr), "l"(gaddr));
}

// ---------------- kernel 2: fp16 GEMM (R11/R14, unchanged) --------------------
__global__ __launch_bounds__(THREADS, 2)
void mma_gemm_kernel(float* __restrict__ C) {
    extern __shared__ __align__(128) char smem[];
    const uint32_t sb = (uint32_t)__cvta_generic_to_shared(smem);

    const int tid  = threadIdx.x;
    const int lane = tid & 31;
    const int wid  = tid >> 5;
    const int wm   = wid & 1;          // 2 warps along M
    const int wn   = wid >> 1;         // 4 warps along N
    const int bx = blockIdx.x;         // E tile (0..3)
    const int by = blockIdx.y;         // batch tile (0..127)
    const int i0 = bx * BN;
    const int kStart = i0;

    const __half* Asrc = g_Xh + (size_t)by * BM * D_DIM;
    const __half* Bsrc = g_Wh + (size_t)i0 * D_DIM;
    int lrow[4], lchk[4];
    #pragma unroll
    for (int i = 0; i < 4; i++) {
        const int v = tid + i * THREADS;   // 0..1023
        lrow[i] = v >> 3;
        lchk[i] = v & 7;
    }

    const uint32_t aoff = ((uint32_t)((wm * 64 + (lane & 15)) * PITCH + (lane >> 4) * 8)) * 2;
    const uint32_t boff = ((uint32_t)((wn * 32 + (lane >> 4) * 8 + (lane & 7)) * PITCH
                                      + ((lane >> 3) & 1) * 8)) * 2;

    float acc[4][4][4];
    #pragma unroll
    for (int mt = 0; mt < 4; mt++)
        #pragma unroll
        for (int nt = 0; nt < 4; nt++)
            #pragma unroll
            for (int q = 0; q < 4; q++) acc[mt][nt][q] = 0.0f;

    auto load_stage = [&](int s, int k0) {
        const uint32_t stg = sb + (uint32_t)s * STAGE_SMEM;
        #pragma unroll
        for (int i = 0; i < 4; i++) {
            const uint32_t so = (uint32_t)(lrow[i] * PITCH * 2 + lchk[i] * 16);
            cp_async16(stg + so,
                       Asrc + (size_t)lrow[i] * D_DIM + k0 + lchk[i] * 8);
            cp_async16(stg + TILE_SMEM + so,
                       Bsrc + (size_t)lrow[i] * D_DIM + k0 + lchk[i] * 8);
        }
        asm volatile("cp.async.commit_group;" ::: "memory");
    };

    load_stage(0, kStart);
    load_stage(1, kStart + BK);
    asm volatile("cp.async.wait_group 1;" ::: "memory");
    __syncthreads();

    for (int it = 0; it < NITER; it++) {
        if (it + 2 < NITER)
            load_stage((it + 2) % STAGES, kStart + (it + 2) * BK);

        const uint32_t stg = sb + (uint32_t)(it % STAGES) * STAGE_SMEM;
        const uint32_t sA = stg + aoff;
        const uint32_t sB = stg + TILE_SMEM + boff;

        #pragma unroll
        for (int k16 = 0; k16 < BK; k16 += 16) {
            const uint32_t ko = k16 * 2;
            uint32_t bfr[8];
            #pragma unroll
            for (int bt = 0; bt < 2; bt++)
                ldm_x4(&bfr[bt * 4], sB + (uint32_t)(bt * 16 * PITCH) * 2 + ko);

            #pragma unroll
            for (int mp = 0; mp < 2; mp++) {
                uint32_t a[8];
                #pragma unroll
                for (int m2 = 0; m2 < 2; m2++)
                    ldm_x4(&a[m2 * 4], sA + (uint32_t)((mp * 2 + m2) * 16 * PITCH) * 2 + ko);
                #pragma unroll
                for (int m2 = 0; m2 < 2; m2++)
                    #pragma unroll
                    for (int nt = 0; nt < 4; nt++)
                        mma_f16(acc[mp * 2 + m2][nt], &a[m2 * 4], &bfr[nt * 2]);
            }
        }

        if (it + 2 < NITER) {
            asm volatile("cp.async.wait_group 1;" ::: "memory");
        } else if (it + 1 < NITER) {
            asm volatile("cp.async.wait_group 0;" ::: "memory");
        }
        __syncthreads();
    }

    const int g = lane >> 2;
    const int c = lane & 3;
    #pragma unroll
    for (int mt = 0; mt < 4; mt++) {
        const int row0 = by * BM + wm * 64 + mt * 16 + g;
        #pragma unroll
        for (int nt = 0; nt < 4; nt++) {
            const int col = i0 + wn * 32 + nt * 8 + c * 2;
            float* p0 = C + (size_t)row0 * E_DIM + col;
            float* p1 = C + (size_t)(row0 + 8) * E_DIM + col;
            *reinterpret_cast<float2*>(p0) = make_float2(acc[mt][nt][0], acc[mt][nt][1]);
            *reinterpret_cast<float2*>(p1) = make_float2(acc[mt][nt][2], acc[mt][nt][3]);
        }
    }
}

// ---------------- kernel 3: bias + L2 normalize (warp per row, no barriers) --
__global__ __launch_bounds__(256)
void bias_normalize_kernel(float* __restrict__ C, const float* __restrict__ b) {
    const int lane = threadIdx.x & 31;
    const int wrp  = threadIdx.x >> 5;           // 0..7
    const int row  = blockIdx.x * 8 + wrp;
    float* Cp = C + (size_t)row * E_DIM;

    float4 v[4], bb[4];
    #pragma unroll
    for (int q = 0; q < 4; q++) {
        v[q]  = reinterpret_cast<float4*>(Cp)[lane + q * 32];
        bb[q] = reinterpret_cast<const float4*>(b)[lane + q * 32];
        v[q].x += bb[q].x; v[q].y += bb[q].y; v[q].z += bb[q].z; v[q].w += bb[q].w;
    }

    float ss = 0.0f;
    #pragma unroll
    for (int q = 0; q < 4; q++)
        ss += v[q].x * v[q].x + v[q].y * v[q].y + v[q].z * v[q].z + v[q].w * v[q].w;
    #pragma unroll
    for (int o = 16; o > 0; o >>= 1) ss += __shfl_xor_sync(0xffffffff, ss, o);

    const float scale = 1.0f / fmaxf(sqrtf(ss), 1e-12f);
    #pragma unroll
    for (int q = 0; q < 4; q++) {
        v[q].x *= scale; v[q].y *= scale; v[q].z *= scale; v[q].w *= scale;
        reinterpret_cast<float4*>(Cp)[lane + q * 32] = v[q];
    }
}

// -----------------------------------------------------------------------------
extern "C" void kernel_launch(void* const* d_in, const int* in_sizes, int n_in,
                              void* d_out, int out_size) {
    const float* x = (const float*)d_in[0];   // (16384, 2048)
    const float* w = (const float*)d_in[1];   // (512, 1537)
    const float* b = (const float*)d_in[2];   // (512,)
    float* out = (float*)d_out;               // (16384, 512)

    cudaFuncSetAttribute(mma_gemm_kernel,
                         cudaFuncAttributeMaxDynamicSharedMemorySize, SMEM_BYTES);

    prep_kernel<<<CONV_BLOCKS + E_DIM, 256>>>(x, w);

    dim3 grid(E_DIM / BN, N_ROWS / BM);       // (4, 128)
    mma_gemm_kernel<<<grid, THREADS, SMEM_BYTES>>>(out);

    bias_normalize_kernel<<<N_ROWS / 8, 256>>>(out, b);
}